// round 14
// baseline (speedup 1.0000x reference)
#include <cuda_runtime.h>
#include <cuda_fp16.h>
#include <cstdint>

#define EPS 1e-5f
#define NB 512
#define NFX 300
#define NP 361
#define AP 264              // A-plane row stride (halfs), K=256 + 8 pad

// per-layer staging strides (halfs) and plane sizes (bytes), k32 chunks
#define WS1 264
#define WS2 136
#define WS3 72
#define PL1 (32 * WS1 * 2)  // 16896
#define PL2 (32 * WS2 * 2)  // 8704
#define PL3 (32 * WS3 * 2)  // 4608

// smem layout (bytes)
#define RU_OFF 1280                      // after 320-float xp (s_e reuses xp region)
#define CV_OFF (RU_OFF + 5 * 256 * 4)    // 6400
#define A_OFF  (CV_OFF + 19 * 256 * 4)   // 25856
#define W_OFF  (A_OFF + 64 * AP * 2)     // 59648
#define SMEM_TOTAL (W_OFF + 2 * PL1)     // 93440 -> 2 CTAs/SM

// ---------------- static device scratch ----------------
__device__ __align__(16) __half g_W1[256 * 256];   // [k][o], NDI weights only
__device__ __align__(16) __half g_W2[256 * 128];
__device__ __align__(16) __half g_W3[128 * 64];
__device__ float g_Wr[16 * 256];         // [i][o] = -wr (row-sum of even w1)
__device__ float g_Wc[16 * 256];         // [j][o] = +wc (col-sum of even w1)
__device__ float g_w4t[256];
__device__ float g_acc[NB * 132];        // per-batch: [0..127] num, [128..131] den

// ---------------- helpers ----------------
__device__ __forceinline__ uint32_t cvta_s(const void* p) {
    uint32_t a; asm("{.reg .u64 t; cvta.to.shared.u64 t,%1; cvt.u32.u64 %0,t;}" : "=r"(a) : "l"(p)); return a;
}
__device__ __forceinline__ void ldmA(uint32_t a, uint32_t r[4]) {
    asm volatile("ldmatrix.sync.aligned.m8n8.x4.shared.b16 {%0,%1,%2,%3},[%4];"
                 : "=r"(r[0]), "=r"(r[1]), "=r"(r[2]), "=r"(r[3]) : "r"(a));
}
__device__ __forceinline__ void ldmBT(uint32_t a, uint32_t r[4]) {
    asm volatile("ldmatrix.sync.aligned.m8n8.x4.trans.shared.b16 {%0,%1,%2,%3},[%4];"
                 : "=r"(r[0]), "=r"(r[1]), "=r"(r[2]), "=r"(r[3]) : "r"(a));
}
__device__ __forceinline__ void mma(float c[4], const uint32_t a[4], uint32_t b0, uint32_t b1) {
    asm volatile("mma.sync.aligned.m16n8k16.row.col.f32.f16.f16.f32 "
                 "{%0,%1,%2,%3},{%4,%5,%6,%7},{%8,%9},{%0,%1,%2,%3};"
                 : "+f"(c[0]), "+f"(c[1]), "+f"(c[2]), "+f"(c[3])
                 : "r"(a[0]), "r"(a[1]), "r"(a[2]), "r"(a[3]), "r"(b0), "r"(b1));
}
__device__ __forceinline__ void cpa16(uint32_t d, const void* s) {
    asm volatile("cp.async.ca.shared.global [%0],[%1],16;" :: "r"(d), "l"(s));
}
#define CP_COMMIT asm volatile("cp.async.commit_group;")
#define CP_WAIT0  asm volatile("cp.async.wait_group 0;")

__device__ __forceinline__ float leaky(float v) { return v >= 0.f ? v : 0.01f * v; }
__device__ __forceinline__ float relu(float v)  { return v > 0.f ? v : 0.f; }

// stage one k32 chunk of a [K][N] fp16 weight matrix (256 threads)
template<int N, int WSN>
__device__ __forceinline__ void stageW(const __half* gw, int chunk, uint32_t dst, int tid) {
    const int ROWU = N / 8;
    const int TOT = 32 * ROWU;
    for (int u = tid; u < TOT; u += 256) {
        int r = u / ROWU, s = u - r * ROWU;
        cpa16(dst + (r * WSN + s * 8) * 2, gw + (size_t)(chunk * 32 + r) * N + s * 8);
    }
}

// 1-term fp16 GEMM, double-buffered (R11 structure). Caller staged+committed chunk 0 into buf 0.
template<int CH, int NFRG, int N, int WSN, int PL>
__device__ __forceinline__ void run_gemm(uint32_t aBase, uint32_t wst, const __half* gW,
                                         float (&acc)[2][NFRG * 2][4],
                                         int wm, int wn, int lane, int tid) {
    const uint32_t aoff = (uint32_t)(((wm * 32 + (lane & 15)) * AP + (lane >> 4) * 8) * 2);
    const int bg = lane >> 3, bi = lane & 7;
    const uint32_t boff = (uint32_t)((((bg & 1) * 8 + bi) * WSN + (bg >> 1) * 8) * 2);
    #pragma unroll 1
    for (int c = 0; c < CH; c++) {
        CP_WAIT0;
        __syncthreads();               // chunk c visible; buffer (c+1)&1 free
        if (c + 1 < CH) {
            stageW<N, WSN>(gW, c + 1, wst + ((c + 1) & 1) * PL, tid);
            CP_COMMIT;
        }
        const uint32_t wb = wst + (c & 1) * PL;
        #pragma unroll
        for (int ks = 0; ks < 2; ks++) {
            uint32_t ab = aBase + aoff + (uint32_t)(c * 2 + ks) * 32;
            uint32_t a0[4], a1[4];
            ldmA(ab, a0);
            ldmA(ab + 16 * AP * 2, a1);
            const uint32_t kb = wb + boff + (uint32_t)ks * 16 * WSN * 2;
            #pragma unroll
            for (int ng = 0; ng < NFRG; ng++) {
                uint32_t nb2 = (uint32_t)(((wn * NFRG + ng) * 16) * 2);
                uint32_t bh[4];
                ldmBT(kb + nb2, bh);
                mma(acc[0][ng * 2 + 0], a0, bh[0], bh[1]);
                mma(acc[0][ng * 2 + 1], a0, bh[2], bh[3]);
                mma(acc[1][ng * 2 + 0], a1, bh[0], bh[1]);
                mma(acc[1][ng * 2 + 1], a1, bh[2], bh[3]);
            }
        }
        __syncthreads();               // release read buffer
    }
}

// ---------------- prep: repack weights + rank-1 sums + zero accumulators ----------------
__global__ void prep_kernel(const float* __restrict__ w1, const float* __restrict__ w2,
                            const float* __restrict__ w3, const float* __restrict__ w4) {
    int idx = blockIdx.x * blockDim.x + threadIdx.x;
    int stride = gridDim.x * blockDim.x;
    // NDI weights: W1[k][o] = w1[o, i*32+j*2+1], i=k>>4, j=k&15
    for (int t = idx; t < 256 * 256; t += stride) {
        int k = t >> 8, o = t & 255;
        int i = k >> 4, j = k & 15;
        g_W1[t] = __float2half_rn(w1[o * 512 + i * 32 + j * 2 + 1]);
    }
    // rank-1 sums (fp32): g_Wr[i][o] = -sum_j w1_even, g_Wc[j][o] = +sum_i w1_even
    for (int t = idx; t < 16 * 256; t += stride) {
        int i = t >> 8, o = t & 255;
        float sr = 0.f, sc = 0.f;
        #pragma unroll
        for (int q = 0; q < 16; q++) {
            sr += w1[o * 512 + i * 32 + q * 2];      // j-sum for row i
            sc += w1[o * 512 + q * 32 + i * 2];      // i-sum for col j=i
        }
        g_Wr[t] = -sr;
        g_Wc[t] = sc;
    }
    for (int t = idx; t < 256 * 128; t += stride) {
        int k = t >> 7, o = t & 127;
        g_W2[t] = __float2half_rn(w2[o * 256 + k]);
    }
    for (int t = idx; t < 128 * 64; t += stride) {
        int k = t >> 6, o = t & 63;
        g_W3[t] = __float2half_rn(w3[o * 128 + k]);
    }
    for (int t = idx; t < 256; t += stride) g_w4t[t] = w4[(t & 3) * 64 + (t >> 2)];
    for (int t = idx; t < NB * 132; t += stride) g_acc[t] = 0.f;
}

// ---------------- main fused kernel: one CTA per (batch, 64-pos tile), 2 CTA/SM ----------------
__global__ __launch_bounds__(256, 2) void mlp_kernel(const float* __restrict__ x,
                                                     const float* __restrict__ b1,
                                                     const float* __restrict__ b2,
                                                     const float* __restrict__ b3,
                                                     const float* __restrict__ b4) {
    extern __shared__ char smem[];
    float* s_xp = (float*)smem;              // 320 floats; reused as s_e later
    float* s_e  = (float*)smem;              // 256 floats (exp weights), after xp is dead
    float* s_Ru = (float*)(smem + RU_OFF);   // [5][256]  b1 + h-term
    float* s_Cv = (float*)(smem + CV_OFF);   // [19][256] w-term
    __half* s_A = (__half*)(smem + A_OFF);
    float* s_h3 = (float*)(smem + W_OFF);    // staging reuse after L3 GEMM: [64][68]
    float* s_part = (float*)(smem + W_OFF + 20480);  // 256 floats partial sums
    const uint32_t sb = cvta_s(smem);
    const uint32_t aBase = sb + A_OFF, wst = sb + W_OFF;

    const int b = blockIdx.x, pos0 = blockIdx.y * 64, tid = threadIdx.x;
    const int lane = tid & 31, ww = tid >> 5;
    const int wm = ww >> 2, wn = ww & 3;     // 2 m-warps x 4 n-warps
    const int r0 = lane >> 2, c0 = (lane & 3) * 2;
    const int h0b = pos0 / 19;

    // stage L1 chunk0 early
    stageW<256, WS1>(g_W1, 0, wst, tid); CP_COMMIT;

    // padded input row
    for (int i = tid; i < 320; i += 256) {
        float v = 0.f;
        if (i >= 2 && i < 302) v = x[b * NFX + i - 2];
        s_xp[i] = v;
    }
    __syncthreads();

    // ---- rank-1 correction tables (fp32): Ru[hh][o] = b1[o] - sum_i u_i(h)*wr[i][o]
    //      Cv[w][o] = sum_j v_j(w)*wc[j][o].  o = tid.
    {
        float wrv[16];
        #pragma unroll
        for (int i = 0; i < 16; i++) wrv[i] = __ldg(&g_Wr[i * 256 + tid]);
        float bb = __ldg(b1 + tid);
        #pragma unroll
        for (int hh = 0; hh < 5; hh++) {
            int h = h0b + hh;                 // may exceed 18; reads land in zero pad
            float s = bb;
            #pragma unroll
            for (int i = 0; i < 16; i++) s += s_xp[i * 19 + h] * wrv[i];
            s_Ru[hh * 256 + tid] = s;
        }
        float wcv[16];
        #pragma unroll
        for (int j = 0; j < 16; j++) wcv[j] = __ldg(&g_Wc[j * 256 + tid]);
        for (int w = 0; w < 19; w++) {
            float s = 0.f;
            #pragma unroll
            for (int j = 0; j < 16; j++) s += s_xp[j * 19 + w] * wcv[j];
            s_Cv[w * 256 + tid] = s;
        }
    }

    // ---- build A (fp16) [64 x 256], NDI only ----
    for (int e = tid; e < 64 * 256; e += 256) {
        int m = e >> 8, k = e & 255;
        int p = pos0 + m, h = p / 19, w = p - h * 19;
        float val = 0.f;
        if (p < NP) {
            int i = k >> 4, j = k & 15;
            float u = s_xp[i * 19 + h], v = s_xp[j * 19 + w];
            val = __fdividef(v - u, u + v + EPS);
        }
        s_A[m * AP + k] = __float2half_rn(val);
    }
    // (run_gemm's first sync orders A/Ru/Cv writes before reads)

    // ================= layer 1: K=256 -> 256 =================
    {
        float acc[2][8][4] = {};
        run_gemm<8, 4, 256, WS1, PL1>(aBase, wst, g_W1, acc, wm, wn, lane, tid);
        stageW<128, WS2>(g_W2, 0, wst, tid); CP_COMMIT;  // pre-stage L2
        #pragma unroll
        for (int mf = 0; mf < 2; mf++) {
            #pragma unroll
            for (int hf = 0; hf < 2; hf++) {
                int row = wm * 32 + mf * 16 + r0 + hf * 8;
                int p = pos0 + row;
                int pc = p > 360 ? 360 : p;
                int h = pc / 19, w = pc - h * 19;
                const float* ru = s_Ru + (h - h0b) * 256;
                const float* cv = s_Cv + w * 256;
                #pragma unroll
                for (int ng = 0; ng < 4; ng++)
                    #pragma unroll
                    for (int e = 0; e < 2; e++) {
                        int col = (wn * 4 + ng) * 16 + e * 8 + c0;
                        const float* a = acc[mf][ng * 2 + e] + hf * 2;
                        float add0 = ru[col] + cv[col], add1 = ru[col + 1] + cv[col + 1];
                        *(__half2*)(s_A + row * AP + col) =
                            __floats2half2_rn(leaky(a[0] + add0), leaky(a[1] + add1));
                    }
            }
        }
    }
    __syncthreads();

    // ================= layer 2: K=256 -> 128 =================
    {
        float acc[2][4][4] = {};
        run_gemm<8, 2, 128, WS2, PL2>(aBase, wst, g_W2, acc, wm, wn, lane, tid);
        stageW<64, WS3>(g_W3, 0, wst, tid); CP_COMMIT;   // pre-stage L3
        #pragma unroll
        for (int mf = 0; mf < 2; mf++) {
            int rb = wm * 32 + mf * 16 + r0;
            #pragma unroll
            for (int ng = 0; ng < 2; ng++)
                #pragma unroll
                for (int e = 0; e < 2; e++) {
                    int col = (wn * 2 + ng) * 16 + e * 8 + c0;
                    const float* a = acc[mf][ng * 2 + e];
                    float bb0 = __ldg(b2 + col), bb1 = __ldg(b2 + col + 1);
                    #pragma unroll
                    for (int hf = 0; hf < 2; hf++) {
                        int row = rb + hf * 8;
                        *(__half2*)(s_A + row * AP + col) =
                            __floats2half2_rn(leaky(a[hf * 2 + 0] + bb0), leaky(a[hf * 2 + 1] + bb1));
                    }
                }
        }
    }
    __syncthreads();

    // ================= layer 3: K=128 -> 64 =================
    {
        float acc[2][2][4] = {};
        run_gemm<4, 1, 64, WS3, PL3>(aBase, wst, g_W3, acc, wm, wn, lane, tid);
        #pragma unroll
        for (int mf = 0; mf < 2; mf++) {
            int rb = wm * 32 + mf * 16 + r0;
            #pragma unroll
            for (int e = 0; e < 2; e++) {
                int col = wn * 16 + e * 8 + c0;
                const float* a = acc[mf][e];
                float bb0 = __ldg(b3 + col), bb1 = __ldg(b3 + col + 1);
                *(float2*)(s_h3 + rb * 68 + col) = make_float2(relu(a[0] + bb0), relu(a[1] + bb1));
                *(float2*)(s_h3 + (rb + 8) * 68 + col) = make_float2(relu(a[2] + bb0), relu(a[3] + bb1));
            }
        }
    }
    __syncthreads();

    // ================= layer 4: logits -> unnormalized exp weights =================
    {
        int m = tid >> 2, oh = tid & 3;      // 256 threads cover 64 rows x 4 heads
        float acc = __ldg(b4 + oh);
        const float* h3 = s_h3 + m * 68;
        #pragma unroll 16
        for (int c = 0; c < 64; c++) acc += h3[c] * __ldg(g_w4t + c * 4 + oh);
        float ev = __expf(relu(acc));
        if (pos0 + m >= NP) ev = 0.f;        // padding rows contribute nothing
        s_e[m * 4 + oh] = ev;
    }
    __syncthreads();

    // ================= fused softmax partials: num[c], den[head] =================
    {
        int c = tid & 127, half = tid >> 7;  // 2 m-halves per channel
        int head = c >> 5;
        float sum = 0.f;
        #pragma unroll 8
        for (int m = half * 32; m < half * 32 + 32; m++)
            sum += s_e[m * 4 + head] * __half2float(s_A[m * AP + c]);
        s_part[half * 128 + c] = sum;
    }
    __syncthreads();
    if (tid < 128) atomicAdd(&g_acc[b * 132 + tid], s_part[tid] + s_part[128 + tid]);
    if (tid < 4) {
        float d = 0.f;
        #pragma unroll 16
        for (int m = 0; m < 64; m++) d += s_e[m * 4 + tid];
        atomicAdd(&g_acc[b * 132 + 128 + tid], d);
    }
}

// ---------------- final divide ----------------
__global__ __launch_bounds__(128) void final_kernel(float* __restrict__ out) {
    int b = blockIdx.x, c = threadIdx.x;
    out[b * 128 + c] = g_acc[b * 132 + c] / g_acc[b * 132 + 128 + (c >> 5)];
}

// ---------------- launch ----------------
extern "C" void kernel_launch(void* const* d_in, const int* in_sizes, int n_in,
                              void* d_out, int out_size) {
    const float* x  = (const float*)d_in[0];
    const float* w1 = (const float*)d_in[1];
    const float* b1 = (const float*)d_in[2];
    const float* w2 = (const float*)d_in[3];
    const float* b2 = (const float*)d_in[4];
    const float* w3 = (const float*)d_in[5];
    const float* b3 = (const float*)d_in[6];
    const float* w4 = (const float*)d_in[7];
    const float* b4 = (const float*)d_in[8];
    float* out = (float*)d_out;

    cudaFuncSetAttribute(mlp_kernel, cudaFuncAttributeMaxDynamicSharedMemorySize, SMEM_TOTAL);

    prep_kernel<<<256, 256>>>(w1, w2, w3, w4);
    mlp_kernel<<<dim3(NB, 6), 256, SMEM_TOTAL>>>(x, b1, b2, b3, b4);
    final_kernel<<<NB, 128>>>(out);
}

// round 15
// speedup vs baseline: 1.0652x; 1.0652x over previous
#include <cuda_runtime.h>
#include <cuda_fp16.h>
#include <cstdint>

#define EPS 1e-5f
#define NB 512
#define NFX 300
#define NP 361
#define AP 296              // A-plane row stride (halfs)

// per-layer staging strides (halfs) and plane sizes (bytes), k32 chunks
#define WS1 264
#define WS2 136
#define WS3 72
#define PL1 (32 * WS1 * 2)  // 16896
#define PL2 (32 * WS2 * 2)  // 8704
#define PL3 (32 * WS3 * 2)  // 4608

#define A_OFF 1280                       // after 320-float xp (+ s_e reuse)
#define W_OFF (A_OFF + 64 * AP * 2)      // 39168
#define SMEM_TOTAL (W_OFF + 2 * PL1)     // 72960  -> 2 CTAs/SM

// ---------------- static device scratch ----------------
__device__ __align__(16) __half g_W1[288 * 256];   // [k][o]
__device__ __align__(16) __half g_W2[256 * 128];
__device__ __align__(16) __half g_W3[128 * 64];
__device__ float g_w4t[256];
__device__ float g_acc[NB * 132];        // per-batch: [0..127] num, [128..131] den (zero-init, self-restoring)
__device__ int   g_cnt[NB];              // per-batch arrival counters (zero-init, self-restoring)

// ---------------- helpers ----------------
__device__ __forceinline__ uint32_t cvta_s(const void* p) {
    uint32_t a; asm("{.reg .u64 t; cvta.to.shared.u64 t,%1; cvt.u32.u64 %0,t;}" : "=r"(a) : "l"(p)); return a;
}
__device__ __forceinline__ void ldmA(uint32_t a, uint32_t r[4]) {
    asm volatile("ldmatrix.sync.aligned.m8n8.x4.shared.b16 {%0,%1,%2,%3},[%4];"
                 : "=r"(r[0]), "=r"(r[1]), "=r"(r[2]), "=r"(r[3]) : "r"(a));
}
__device__ __forceinline__ void ldmBT(uint32_t a, uint32_t r[4]) {
    asm volatile("ldmatrix.sync.aligned.m8n8.x4.trans.shared.b16 {%0,%1,%2,%3},[%4];"
                 : "=r"(r[0]), "=r"(r[1]), "=r"(r[2]), "=r"(r[3]) : "r"(a));
}
__device__ __forceinline__ void mma(float c[4], const uint32_t a[4], uint32_t b0, uint32_t b1) {
    asm volatile("mma.sync.aligned.m16n8k16.row.col.f32.f16.f16.f32 "
                 "{%0,%1,%2,%3},{%4,%5,%6,%7},{%8,%9},{%0,%1,%2,%3};"
                 : "+f"(c[0]), "+f"(c[1]), "+f"(c[2]), "+f"(c[3])
                 : "r"(a[0]), "r"(a[1]), "r"(a[2]), "r"(a[3]), "r"(b0), "r"(b1));
}
__device__ __forceinline__ void cpa16(uint32_t d, const void* s) {
    asm volatile("cp.async.ca.shared.global [%0],[%1],16;" :: "r"(d), "l"(s));
}
#define CP_COMMIT asm volatile("cp.async.commit_group;")
#define CP_WAIT0  asm volatile("cp.async.wait_group 0;")

__device__ __forceinline__ float leaky(float v) { return v >= 0.f ? v : 0.01f * v; }
__device__ __forceinline__ float relu(float v)  { return v > 0.f ? v : 0.f; }

// stage one k32 chunk of a [K][N] fp16 weight matrix (256 threads)
template<int N, int WSN>
__device__ __forceinline__ void stageW(const __half* gw, int chunk, uint32_t dst, int tid) {
    const int ROWU = N / 8;
    const int TOT = 32 * ROWU;
    for (int u = tid; u < TOT; u += 256) {
        int r = u / ROWU, s = u - r * ROWU;
        cpa16(dst + (r * WSN + s * 8) * 2, gw + (size_t)(chunk * 32 + r) * N + s * 8);
    }
}

// 1-term fp16 GEMM, double-buffered. Caller must have staged+committed chunk 0 into buf 0.
template<int CH, int NFRG, int N, int WSN, int PL>
__device__ __forceinline__ void run_gemm(uint32_t aBase, uint32_t wst, const __half* gW,
                                         float (&acc)[2][NFRG * 2][4],
                                         int wm, int wn, int lane, int tid) {
    const uint32_t aoff = (uint32_t)(((wm * 32 + (lane & 15)) * AP + (lane >> 4) * 8) * 2);
    const int bg = lane >> 3, bi = lane & 7;
    const uint32_t boff = (uint32_t)((((bg & 1) * 8 + bi) * WSN + (bg >> 1) * 8) * 2);
    #pragma unroll 1
    for (int c = 0; c < CH; c++) {
        CP_WAIT0;
        __syncthreads();               // chunk c visible; buffer (c+1)&1 free
        if (c + 1 < CH) {
            stageW<N, WSN>(gW, c + 1, wst + ((c + 1) & 1) * PL, tid);
            CP_COMMIT;
        }
        const uint32_t wb = wst + (c & 1) * PL;
        #pragma unroll
        for (int ks = 0; ks < 2; ks++) {
            uint32_t ab = aBase + aoff + (uint32_t)(c * 2 + ks) * 32;
            uint32_t a0[4], a1[4];
            ldmA(ab, a0);
            ldmA(ab + 16 * AP * 2, a1);
            const uint32_t kb = wb + boff + (uint32_t)ks * 16 * WSN * 2;
            #pragma unroll
            for (int ng = 0; ng < NFRG; ng++) {
                uint32_t nb2 = (uint32_t)(((wn * NFRG + ng) * 16) * 2);
                uint32_t bh[4];
                ldmBT(kb + nb2, bh);
                mma(acc[0][ng * 2 + 0], a0, bh[0], bh[1]);
                mma(acc[0][ng * 2 + 1], a0, bh[2], bh[3]);
                mma(acc[1][ng * 2 + 0], a1, bh[0], bh[1]);
                mma(acc[1][ng * 2 + 1], a1, bh[2], bh[3]);
            }
        }
        __syncthreads();               // release read buffer
    }
}

// ---------------- prep: repack weights to fp16 [k][o] ----------------
__global__ void prep_kernel(const float* __restrict__ w1, const float* __restrict__ w2,
                            const float* __restrict__ w3, const float* __restrict__ w4) {
    int idx = blockIdx.x * blockDim.x + threadIdx.x;
    int stride = gridDim.x * blockDim.x;
    // layer 1 combined K=288: k<256 NDI weight (i=k>>4,j=k&15); 256..271: -wr[i]; 272..287: +wc[j]
    for (int t = idx; t < 288 * 256; t += stride) {
        int k = t >> 8, o = t & 255;
        float v;
        if (k < 256) {
            int i = k >> 4, j = k & 15;
            v = w1[o * 512 + i * 32 + j * 2 + 1];
        } else if (k < 272) {
            int i = k - 256; float s = 0.f;
            #pragma unroll
            for (int j = 0; j < 16; j++) s += w1[o * 512 + i * 32 + j * 2];
            v = -s;
        } else {
            int j = k - 272; float s = 0.f;
            #pragma unroll
            for (int i = 0; i < 16; i++) s += w1[o * 512 + i * 32 + j * 2];
            v = s;
        }
        g_W1[t] = __float2half_rn(v);
    }
    for (int t = idx; t < 256 * 128; t += stride) {
        int k = t >> 7, o = t & 127;
        g_W2[t] = __float2half_rn(w2[o * 256 + k]);
    }
    for (int t = idx; t < 128 * 64; t += stride) {
        int k = t >> 6, o = t & 63;
        g_W3[t] = __float2half_rn(w3[o * 128 + k]);
    }
    for (int t = idx; t < 256; t += stride) g_w4t[t] = w4[(t & 3) * 64 + (t >> 2)];
}

// ---------------- main fused kernel: one CTA per (batch, 64-pos tile), 2 CTA/SM ----------------
__global__ __launch_bounds__(256, 2) void mlp_kernel(const float* __restrict__ x,
                                                     const float* __restrict__ b1,
                                                     const float* __restrict__ b2,
                                                     const float* __restrict__ b3,
                                                     const float* __restrict__ b4,
                                                     float* __restrict__ out) {
    extern __shared__ char smem[];
    float* s_xp = (float*)smem;              // 320 floats; reused as s_e later
    float* s_e  = (float*)smem;              // 256 floats (exp weights), after xp is dead
    __half* s_A = (__half*)(smem + A_OFF);
    float* s_h3 = (float*)(smem + W_OFF);    // staging area reuse after L3 GEMM: [64][68]
    float* s_part = (float*)(smem + W_OFF + 20480);  // 256 floats partial sums
    __shared__ int s_last;
    const uint32_t sb = cvta_s(smem);
    const uint32_t aBase = sb + A_OFF, wst = sb + W_OFF;

    const int b = blockIdx.x, pos0 = blockIdx.y * 64, tid = threadIdx.x;
    const int lane = tid & 31, ww = tid >> 5;
    const int wm = ww >> 2, wn = ww & 3;     // 2 m-warps x 4 n-warps
    const int r0 = lane >> 2, c0 = (lane & 3) * 2;

    // stage L1 chunk0 early
    stageW<256, WS1>(g_W1, 0, wst, tid); CP_COMMIT;

    // padded input row
    for (int i = tid; i < 320; i += 256) {
        float v = 0.f;
        if (i >= 2 && i < 302) v = x[b * NFX + i - 2];
        s_xp[i] = v;
    }
    __syncthreads();

    // ---- build A (fp16) [64 x 288] ----
    for (int e = tid; e < 64 * 288; e += 256) {
        int m = e / 288, k = e - m * 288;
        int p = pos0 + m, h = p / 19, w = p - h * 19;
        float val = 0.f;
        if (p < NP) {
            if (k < 256) {
                int i = k >> 4, j = k & 15;
                float u = s_xp[i * 19 + h], v = s_xp[j * 19 + w];
                val = __fdividef(v - u, u + v + EPS);
            } else if (k < 272) {
                val = s_xp[(k - 256) * 19 + h];
            } else {
                val = s_xp[(k - 272) * 19 + w];
            }
        }
        s_A[m * AP + k] = __float2half_rn(val);
    }
    // (run_gemm's first internal __syncthreads orders A writes before ldmatrix)

    // ================= layer 1: K=288 -> 256 =================
    {
        float acc[2][8][4] = {};
        run_gemm<9, 4, 256, WS1, PL1>(aBase, wst, g_W1, acc, wm, wn, lane, tid);
        stageW<128, WS2>(g_W2, 0, wst, tid); CP_COMMIT;  // pre-stage L2
        #pragma unroll
        for (int mf = 0; mf < 2; mf++) {
            int rb = wm * 32 + mf * 16 + r0;
            #pragma unroll
            for (int ng = 0; ng < 4; ng++)
                #pragma unroll
                for (int e = 0; e < 2; e++) {
                    int col = (wn * 4 + ng) * 16 + e * 8 + c0;
                    const float* a = acc[mf][ng * 2 + e];
                    float bb0 = __ldg(b1 + col), bb1 = __ldg(b1 + col + 1);
                    *(__half2*)(s_A + rb * AP + col) =
                        __floats2half2_rn(leaky(a[0] + bb0), leaky(a[1] + bb1));
                    *(__half2*)(s_A + (rb + 8) * AP + col) =
                        __floats2half2_rn(leaky(a[2] + bb0), leaky(a[3] + bb1));
                }
        }
    }
    __syncthreads();

    // ================= layer 2: K=256 -> 128 =================
    {
        float acc[2][4][4] = {};
        run_gemm<8, 2, 128, WS2, PL2>(aBase, wst, g_W2, acc, wm, wn, lane, tid);
        stageW<64, WS3>(g_W3, 0, wst, tid); CP_COMMIT;   // pre-stage L3
        #pragma unroll
        for (int mf = 0; mf < 2; mf++) {
            int rb = wm * 32 + mf * 16 + r0;
            #pragma unroll
            for (int ng = 0; ng < 2; ng++)
                #pragma unroll
                for (int e = 0; e < 2; e++) {
                    int col = (wn * 2 + ng) * 16 + e * 8 + c0;
                    const float* a = acc[mf][ng * 2 + e];
                    float bb0 = __ldg(b2 + col), bb1 = __ldg(b2 + col + 1);
                    #pragma unroll
                    for (int hf = 0; hf < 2; hf++) {
                        int row = rb + hf * 8;
                        *(__half2*)(s_A + row * AP + col) =
                            __floats2half2_rn(leaky(a[hf * 2 + 0] + bb0), leaky(a[hf * 2 + 1] + bb1));
                    }
                }
        }
    }
    __syncthreads();

    // ================= layer 3: K=128 -> 64 =================
    {
        float acc[2][2][4] = {};
        run_gemm<4, 1, 64, WS3, PL3>(aBase, wst, g_W3, acc, wm, wn, lane, tid);
        #pragma unroll
        for (int mf = 0; mf < 2; mf++) {
            int rb = wm * 32 + mf * 16 + r0;
            #pragma unroll
            for (int e = 0; e < 2; e++) {
                int col = wn * 16 + e * 8 + c0;
                const float* a = acc[mf][e];
                float bb0 = __ldg(b3 + col), bb1 = __ldg(b3 + col + 1);
                *(float2*)(s_h3 + rb * 68 + col) = make_float2(relu(a[0] + bb0), relu(a[1] + bb1));
                *(float2*)(s_h3 + (rb + 8) * 68 + col) = make_float2(relu(a[2] + bb0), relu(a[3] + bb1));
            }
        }
    }
    __syncthreads();

    // ================= layer 4: logits -> unnormalized exp weights =================
    {
        int m = tid >> 2, oh = tid & 3;      // 256 threads cover 64 rows x 4 heads
        float acc = __ldg(b4 + oh);
        const float* h3 = s_h3 + m * 68;
        #pragma unroll 16
        for (int c = 0; c < 64; c++) acc += h3[c] * __ldg(g_w4t + c * 4 + oh);
        float ev = __expf(relu(acc));
        if (pos0 + m >= NP) ev = 0.f;        // padding rows contribute nothing
        s_e[m * 4 + oh] = ev;
    }
    __syncthreads();

    // ================= fused softmax partials: num[c], den[head] =================
    {
        int c = tid & 127, half = tid >> 7;  // 2 m-halves per channel
        int head = c >> 5;
        float sum = 0.f;
        #pragma unroll 8
        for (int m = half * 32; m < half * 32 + 32; m++)
            sum += s_e[m * 4 + head] * __half2float(s_A[m * AP + c]);
        s_part[half * 128 + c] = sum;
    }
    __syncthreads();
    if (tid < 128) atomicAdd(&g_acc[b * 132 + tid], s_part[tid] + s_part[128 + tid]);
    if (tid < 4) {
        float d = 0.f;
        #pragma unroll 16
        for (int m = 0; m < 64; m++) d += s_e[m * 4 + tid];
        atomicAdd(&g_acc[b * 132 + 128 + tid], d);
    }

    // ================= in-kernel finalization (last CTA of batch) =================
    __threadfence();                         // all threads: flush partials before counting
    __syncthreads();
    if (tid == 0) s_last = (atomicAdd(&g_cnt[b], 1) == 5);
    __syncthreads();
    if (s_last) {
        float num = 0.f, den = 1.f;
        if (tid < 128) {
            num = __ldcg(&g_acc[b * 132 + tid]);
            den = __ldcg(&g_acc[b * 132 + 128 + (tid >> 5)]);
        }
        __syncthreads();                     // reads done before re-zeroing
        if (tid < 128) {
            out[b * 128 + tid] = num / den;
            g_acc[b * 132 + tid] = 0.f;      // restore invariant for next replay
        }
        if (tid < 4) g_acc[b * 132 + 128 + tid] = 0.f;
        __threadfence();
        if (tid == 0) atomicExch(&g_cnt[b], 0);
    }
}

// ---------------- launch ----------------
extern "C" void kernel_launch(void* const* d_in, const int* in_sizes, int n_in,
                              void* d_out, int out_size) {
    const float* x  = (const float*)d_in[0];
    const float* w1 = (const float*)d_in[1];
    const float* b1 = (const float*)d_in[2];
    const float* w2 = (const float*)d_in[3];
    const float* b2 = (const float*)d_in[4];
    const float* w3 = (const float*)d_in[5];
    const float* b3 = (const float*)d_in[6];
    const float* w4 = (const float*)d_in[7];
    const float* b4 = (const float*)d_in[8];
    float* out = (float*)d_out;

    cudaFuncSetAttribute(mlp_kernel, cudaFuncAttributeMaxDynamicSharedMemorySize, SMEM_TOTAL);

    prep_kernel<<<512, 256>>>(w1, w2, w3, w4);
    mlp_kernel<<<dim3(NB, 6), 256, SMEM_TOTAL>>>(x, b1, b2, b3, b4, out);
}

// round 16
// speedup vs baseline: 1.1136x; 1.0454x over previous
#include <cuda_runtime.h>
#include <cuda_fp16.h>
#include <cstdint>

#define EPS 1e-5f
#define NB 512
#define NFX 300
#define NP 361
#define AP 296              // A-plane row stride (halfs)

// per-layer staging strides (halfs) and plane sizes (bytes), k32 chunks
#define WS1 264
#define WS2 136
#define WS3 72
#define PL1 (32 * WS1 * 2)  // 16896
#define PL2 (32 * WS2 * 2)  // 8704
#define PL3 (32 * WS3 * 2)  // 4608

#define W4_OFF 1280                      // 256-float w4t table (after 320-float xp)
#define A_OFF  2304                      // A plane
#define W_OFF  (A_OFF + 64 * AP * 2)     // 40192
#define SMEM_TOTAL (W_OFF + 2 * PL1)     // 73984 -> 2 CTAs/SM

// ---------------- static device scratch ----------------
__device__ __align__(16) __half g_W1[288 * 256];   // [k][o]
__device__ __align__(16) __half g_W2[256 * 128];
__device__ __align__(16) __half g_W3[128 * 64];
__device__ float g_w4t[256];
__device__ float g_acc[NB * 132];        // per-batch: [0..127] num, [128..131] den

// ---------------- helpers ----------------
__device__ __forceinline__ uint32_t cvta_s(const void* p) {
    uint32_t a; asm("{.reg .u64 t; cvta.to.shared.u64 t,%1; cvt.u32.u64 %0,t;}" : "=r"(a) : "l"(p)); return a;
}
__device__ __forceinline__ void ldmA(uint32_t a, uint32_t r[4]) {
    asm volatile("ldmatrix.sync.aligned.m8n8.x4.shared.b16 {%0,%1,%2,%3},[%4];"
                 : "=r"(r[0]), "=r"(r[1]), "=r"(r[2]), "=r"(r[3]) : "r"(a));
}
__device__ __forceinline__ void ldmBT(uint32_t a, uint32_t r[4]) {
    asm volatile("ldmatrix.sync.aligned.m8n8.x4.trans.shared.b16 {%0,%1,%2,%3},[%4];"
                 : "=r"(r[0]), "=r"(r[1]), "=r"(r[2]), "=r"(r[3]) : "r"(a));
}
__device__ __forceinline__ void mma(float c[4], const uint32_t a[4], uint32_t b0, uint32_t b1) {
    asm volatile("mma.sync.aligned.m16n8k16.row.col.f32.f16.f16.f32 "
                 "{%0,%1,%2,%3},{%4,%5,%6,%7},{%8,%9},{%0,%1,%2,%3};"
                 : "+f"(c[0]), "+f"(c[1]), "+f"(c[2]), "+f"(c[3])
                 : "r"(a[0]), "r"(a[1]), "r"(a[2]), "r"(a[3]), "r"(b0), "r"(b1));
}
__device__ __forceinline__ void cpa16(uint32_t d, const void* s) {
    asm volatile("cp.async.ca.shared.global [%0],[%1],16;" :: "r"(d), "l"(s));
}
#define CP_COMMIT asm volatile("cp.async.commit_group;")
#define CP_WAIT0  asm volatile("cp.async.wait_group 0;")

__device__ __forceinline__ float leaky(float v) { return v >= 0.f ? v : 0.01f * v; }
__device__ __forceinline__ float relu(float v)  { return v > 0.f ? v : 0.f; }

// stage one k32 chunk of a [K][N] fp16 weight matrix (256 threads)
template<int N, int WSN>
__device__ __forceinline__ void stageW(const __half* gw, int chunk, uint32_t dst, int tid) {
    const int ROWU = N / 8;
    const int TOT = 32 * ROWU;
    for (int u = tid; u < TOT; u += 256) {
        int r = u / ROWU, s = u - r * ROWU;
        cpa16(dst + (r * WSN + s * 8) * 2, gw + (size_t)(chunk * 32 + r) * N + s * 8);
    }
}

// 1-term fp16 GEMM, double-buffered. Caller must have staged+committed chunk 0 into buf 0.
template<int CH, int NFRG, int N, int WSN, int PL>
__device__ __forceinline__ void run_gemm(uint32_t aBase, uint32_t wst, const __half* gW,
                                         float (&acc)[2][NFRG * 2][4],
                                         int wm, int wn, int lane, int tid) {
    const uint32_t aoff = (uint32_t)(((wm * 32 + (lane & 15)) * AP + (lane >> 4) * 8) * 2);
    const int bg = lane >> 3, bi = lane & 7;
    const uint32_t boff = (uint32_t)((((bg & 1) * 8 + bi) * WSN + (bg >> 1) * 8) * 2);
    #pragma unroll 1
    for (int c = 0; c < CH; c++) {
        CP_WAIT0;
        __syncthreads();               // chunk c visible; buffer (c+1)&1 free
        if (c + 1 < CH) {
            stageW<N, WSN>(gW, c + 1, wst + ((c + 1) & 1) * PL, tid);
            CP_COMMIT;
        }
        const uint32_t wb = wst + (c & 1) * PL;
        #pragma unroll
        for (int ks = 0; ks < 2; ks++) {
            uint32_t ab = aBase + aoff + (uint32_t)(c * 2 + ks) * 32;
            uint32_t a0[4], a1[4];
            ldmA(ab, a0);
            ldmA(ab + 16 * AP * 2, a1);
            const uint32_t kb = wb + boff + (uint32_t)ks * 16 * WSN * 2;
            #pragma unroll
            for (int ng = 0; ng < NFRG; ng++) {
                uint32_t nb2 = (uint32_t)(((wn * NFRG + ng) * 16) * 2);
                uint32_t bh[4];
                ldmBT(kb + nb2, bh);
                mma(acc[0][ng * 2 + 0], a0, bh[0], bh[1]);
                mma(acc[0][ng * 2 + 1], a0, bh[2], bh[3]);
                mma(acc[1][ng * 2 + 0], a1, bh[0], bh[1]);
                mma(acc[1][ng * 2 + 1], a1, bh[2], bh[3]);
            }
        }
        __syncthreads();               // release read buffer
    }
}

// ---------------- prep: repack weights to fp16 [k][o] ----------------
__global__ void prep_kernel(const float* __restrict__ w1, const float* __restrict__ w2,
                            const float* __restrict__ w3, const float* __restrict__ w4) {
    int idx = blockIdx.x * blockDim.x + threadIdx.x;
    int stride = gridDim.x * blockDim.x;
    // layer 1 combined K=288: k<256 NDI weight (i=k>>4,j=k&15); 256..271: -wr[i]; 272..287: +wc[j]
    for (int t = idx; t < 288 * 256; t += stride) {
        int k = t >> 8, o = t & 255;
        float v;
        if (k < 256) {
            int i = k >> 4, j = k & 15;
            v = w1[o * 512 + i * 32 + j * 2 + 1];
        } else if (k < 272) {
            int i = k - 256; float s = 0.f;
            #pragma unroll
            for (int j = 0; j < 16; j++) s += w1[o * 512 + i * 32 + j * 2];
            v = -s;
        } else {
            int j = k - 272; float s = 0.f;
            #pragma unroll
            for (int i = 0; i < 16; i++) s += w1[o * 512 + i * 32 + j * 2];
            v = s;
        }
        g_W1[t] = __float2half_rn(v);
    }
    for (int t = idx; t < 256 * 128; t += stride) {
        int k = t >> 7, o = t & 127;
        g_W2[t] = __float2half_rn(w2[o * 256 + k]);
    }
    for (int t = idx; t < 128 * 64; t += stride) {
        int k = t >> 6, o = t & 63;
        g_W3[t] = __float2half_rn(w3[o * 128 + k]);
    }
    for (int t = idx; t < 256; t += stride) g_w4t[t] = w4[(t & 3) * 64 + (t >> 2)];
}

// ---------------- zero accumulators (graph-replay safe) ----------------
__global__ void zero_kernel() {
    int i = blockIdx.x * blockDim.x + threadIdx.x;
    if (i < NB * 132) g_acc[i] = 0.f;
}

// ---------------- main fused kernel: one CTA per (batch, 64-pos tile), 2 CTA/SM ----------------
__global__ __launch_bounds__(256, 2) void mlp_kernel(const float* __restrict__ x,
                                                     const float* __restrict__ b1,
                                                     const float* __restrict__ b2,
                                                     const float* __restrict__ b3,
                                                     const float* __restrict__ b4) {
    extern __shared__ char smem[];
    float* s_xp = (float*)smem;              // 320 floats; reused as s_e later
    float* s_e  = (float*)smem;              // 256 floats (exp weights), after xp is dead
    float* s_w4 = (float*)(smem + W4_OFF);   // 256 floats w4t
    __half* s_A = (__half*)(smem + A_OFF);
    float* s_h3 = (float*)(smem + W_OFF);    // staging area reuse after L3 GEMM: [64][68]
    float* s_part = (float*)(smem + W_OFF + 20480);  // 256 floats partial sums
    const uint32_t sb = cvta_s(smem);
    const uint32_t aBase = sb + A_OFF, wst = sb + W_OFF;

    const int b = blockIdx.x, pos0 = blockIdx.y * 64, tid = threadIdx.x;
    const int lane = tid & 31, ww = tid >> 5;
    const int wm = ww >> 2, wn = ww & 3;     // 2 m-warps x 4 n-warps
    const int r0 = lane >> 2, c0 = (lane & 3) * 2;

    // stage L1 chunk0 early
    stageW<256, WS1>(g_W1, 0, wst, tid); CP_COMMIT;

    // padded input row + w4 table
    for (int i = tid; i < 320; i += 256) {
        float v = 0.f;
        if (i >= 2 && i < 302) v = x[b * NFX + i - 2];
        s_xp[i] = v;
    }
    s_w4[tid] = g_w4t[tid];
    __syncthreads();

    // ---- build A (fp16) [64 x 288]: 4 threads per row, 72 contiguous k each ----
    {
        const int m = tid >> 2, k0 = (tid & 3) * 72;
        const int p = pos0 + m, h = p / 19, w = p - h * 19;
        const bool pv = (p < NP);
        __half* dst = s_A + m * AP;
        #pragma unroll 4
        for (int kk = 0; kk < 72; kk++) {
            int k = k0 + kk;
            float val = 0.f;
            if (pv) {
                if (k < 256) {
                    int i = k >> 4, j = k & 15;
                    float u = s_xp[i * 19 + h], v = s_xp[j * 19 + w];
                    val = __fdividef(v - u, u + v + EPS);
                } else if (k < 272) {
                    val = s_xp[(k - 256) * 19 + h];
                } else {
                    val = s_xp[(k - 272) * 19 + w];
                }
            }
            dst[k] = __float2half_rn(val);
        }
    }
    // (run_gemm's first internal __syncthreads orders A writes before ldmatrix)

    // ================= layer 1: K=288 -> 256 =================
    {
        float acc[2][8][4] = {};
        run_gemm<9, 4, 256, WS1, PL1>(aBase, wst, g_W1, acc, wm, wn, lane, tid);
        stageW<128, WS2>(g_W2, 0, wst, tid); CP_COMMIT;  // pre-stage L2
        #pragma unroll
        for (int mf = 0; mf < 2; mf++) {
            int rb = wm * 32 + mf * 16 + r0;
            #pragma unroll
            for (int ng = 0; ng < 4; ng++)
                #pragma unroll
                for (int e = 0; e < 2; e++) {
                    int col = (wn * 4 + ng) * 16 + e * 8 + c0;
                    const float* a = acc[mf][ng * 2 + e];
                    float bb0 = __ldg(b1 + col), bb1 = __ldg(b1 + col + 1);
                    *(__half2*)(s_A + rb * AP + col) =
                        __floats2half2_rn(leaky(a[0] + bb0), leaky(a[1] + bb1));
                    *(__half2*)(s_A + (rb + 8) * AP + col) =
                        __floats2half2_rn(leaky(a[2] + bb0), leaky(a[3] + bb1));
                }
        }
    }
    __syncthreads();

    // ================= layer 2: K=256 -> 128 =================
    {
        float acc[2][4][4] = {};
        run_gemm<8, 2, 128, WS2, PL2>(aBase, wst, g_W2, acc, wm, wn, lane, tid);
        stageW<64, WS3>(g_W3, 0, wst, tid); CP_COMMIT;   // pre-stage L3
        #pragma unroll
        for (int mf = 0; mf < 2; mf++) {
            int rb = wm * 32 + mf * 16 + r0;
            #pragma unroll
            for (int ng = 0; ng < 2; ng++)
                #pragma unroll
                for (int e = 0; e < 2; e++) {
                    int col = (wn * 2 + ng) * 16 + e * 8 + c0;
                    const float* a = acc[mf][ng * 2 + e];
                    float bb0 = __ldg(b2 + col), bb1 = __ldg(b2 + col + 1);
                    #pragma unroll
                    for (int hf = 0; hf < 2; hf++) {
                        int row = rb + hf * 8;
                        *(__half2*)(s_A + row * AP + col) =
                            __floats2half2_rn(leaky(a[hf * 2 + 0] + bb0), leaky(a[hf * 2 + 1] + bb1));
                    }
                }
        }
    }
    __syncthreads();

    // ================= layer 3: K=128 -> 64 =================
    {
        float acc[2][2][4] = {};
        run_gemm<4, 1, 64, WS3, PL3>(aBase, wst, g_W3, acc, wm, wn, lane, tid);
        #pragma unroll
        for (int mf = 0; mf < 2; mf++) {
            int rb = wm * 32 + mf * 16 + r0;
            #pragma unroll
            for (int e = 0; e < 2; e++) {
                int col = wn * 16 + e * 8 + c0;
                const float* a = acc[mf][e];
                float bb0 = __ldg(b3 + col), bb1 = __ldg(b3 + col + 1);
                *(float2*)(s_h3 + rb * 68 + col) = make_float2(relu(a[0] + bb0), relu(a[1] + bb1));
                *(float2*)(s_h3 + (rb + 8) * 68 + col) = make_float2(relu(a[2] + bb0), relu(a[3] + bb1));
            }
        }
    }
    __syncthreads();

    // ================= layer 4: logits -> unnormalized exp weights =================
    {
        int m = tid >> 2, oh = tid & 3;      // 256 threads cover 64 rows x 4 heads
        float acc = __ldg(b4 + oh);
        const float* h3 = s_h3 + m * 68;
        #pragma unroll 16
        for (int c = 0; c < 64; c++) acc += h3[c] * s_w4[c * 4 + oh];
        float ev = __expf(relu(acc));
        if (pos0 + m >= NP) ev = 0.f;        // padding rows contribute nothing
        s_e[m * 4 + oh] = ev;
    }
    __syncthreads();

    // ================= fused softmax partials: num[c], den[head] =================
    {
        int c = tid & 127, half = tid >> 7;  // 2 m-halves per channel
        int head = c >> 5;
        float sum = 0.f;
        #pragma unroll 8
        for (int m = half * 32; m < half * 32 + 32; m++)
            sum += s_e[m * 4 + head] * __half2float(s_A[m * AP + c]);
        s_part[half * 128 + c] = sum;
    }
    __syncthreads();
    if (tid < 128) atomicAdd(&g_acc[b * 132 + tid], s_part[tid] + s_part[128 + tid]);
    if (tid < 4) {
        float d = 0.f;
        #pragma unroll 16
        for (int m = 0; m < 64; m++) d += s_e[m * 4 + tid];
        atomicAdd(&g_acc[b * 132 + 128 + tid], d);
    }
}

// ---------------- final divide ----------------
__global__ __launch_bounds__(128) void final_kernel(float* __restrict__ out) {
    int b = blockIdx.x, c = threadIdx.x;
    out[b * 128 + c] = g_acc[b * 132 + c] / g_acc[b * 132 + 128 + (c >> 5)];
}

// ---------------- launch ----------------
extern "C" void kernel_launch(void* const* d_in, const int* in_sizes, int n_in,
                              void* d_out, int out_size) {
    const float* x  = (const float*)d_in[0];
    const float* w1 = (const float*)d_in[1];
    const float* b1 = (const float*)d_in[2];
    const float* w2 = (const float*)d_in[3];
    const float* b2 = (const float*)d_in[4];
    const float* w3 = (const float*)d_in[5];
    const float* b3 = (const float*)d_in[6];
    const float* w4 = (const float*)d_in[7];
    const float* b4 = (const float*)d_in[8];
    float* out = (float*)d_out;

    cudaFuncSetAttribute(mlp_kernel, cudaFuncAttributeMaxDynamicSharedMemorySize, SMEM_TOTAL);

    prep_kernel<<<512, 256>>>(w1, w2, w3, w4);
    zero_kernel<<<(NB * 132 + 255) / 256, 256>>>();
    mlp_kernel<<<dim3(NB, 6), 256, SMEM_TOTAL>>>(x, b1, b2, b3, b4);
    final_kernel<<<NB, 128>>>(out);
}

// round 17
// speedup vs baseline: 1.1290x; 1.0139x over previous
#include <cuda_runtime.h>
#include <cuda_fp16.h>
#include <cstdint>

#define EPS 1e-5f
#define NB 512
#define NFX 300
#define NP 361
#define AP 296              // A-plane row stride (halfs)

// per-layer staging strides (halfs) and plane sizes (bytes), k32 chunks
#define WS1 264
#define WS2 136
#define WS3 72
#define PL1 (32 * WS1 * 2)  // 16896
#define PL2 (32 * WS2 * 2)  // 8704
#define PL3 (32 * WS3 * 2)  // 4608

#define W4_OFF 1280                      // 256-float w4t table (after 320-float xp)
#define A_OFF  2304                      // A plane
#define W_OFF  (A_OFF + 64 * AP * 2)     // 40192
#define SMEM_TOTAL (W_OFF + 2 * PL1)     // 73984 -> 2 CTAs/SM

// ---------------- static device scratch ----------------
__device__ __align__(16) __half g_W1[288 * 256];   // [k][o]
__device__ __align__(16) __half g_W2[256 * 128];
__device__ __align__(16) __half g_W3[128 * 64];
__device__ float g_w4t[256];
__device__ float g_acc[NB * 132];        // per-batch: [0..127] num, [128..131] den

// ---------------- helpers ----------------
__device__ __forceinline__ uint32_t cvta_s(const void* p) {
    uint32_t a; asm("{.reg .u64 t; cvta.to.shared.u64 t,%1; cvt.u32.u64 %0,t;}" : "=r"(a) : "l"(p)); return a;
}
__device__ __forceinline__ void ldmA(uint32_t a, uint32_t r[4]) {
    asm volatile("ldmatrix.sync.aligned.m8n8.x4.shared.b16 {%0,%1,%2,%3},[%4];"
                 : "=r"(r[0]), "=r"(r[1]), "=r"(r[2]), "=r"(r[3]) : "r"(a));
}
__device__ __forceinline__ void ldmBT(uint32_t a, uint32_t r[4]) {
    asm volatile("ldmatrix.sync.aligned.m8n8.x4.trans.shared.b16 {%0,%1,%2,%3},[%4];"
                 : "=r"(r[0]), "=r"(r[1]), "=r"(r[2]), "=r"(r[3]) : "r"(a));
}
// stmatrix: write one 16x16 b16 tile from C-fragment-layout registers (4 wavefronts)
__device__ __forceinline__ void stmA(uint32_t a, uint32_t r0, uint32_t r1, uint32_t r2, uint32_t r3) {
    asm volatile("stmatrix.sync.aligned.m8n8.x4.shared.b16 [%0], {%1,%2,%3,%4};"
                 :: "r"(a), "r"(r0), "r"(r1), "r"(r2), "r"(r3) : "memory");
}
__device__ __forceinline__ void mma(float c[4], const uint32_t a[4], uint32_t b0, uint32_t b1) {
    asm volatile("mma.sync.aligned.m16n8k16.row.col.f32.f16.f16.f32 "
                 "{%0,%1,%2,%3},{%4,%5,%6,%7},{%8,%9},{%0,%1,%2,%3};"
                 : "+f"(c[0]), "+f"(c[1]), "+f"(c[2]), "+f"(c[3])
                 : "r"(a[0]), "r"(a[1]), "r"(a[2]), "r"(a[3]), "r"(b0), "r"(b1));
}
__device__ __forceinline__ void cpa16(uint32_t d, const void* s) {
    asm volatile("cp.async.ca.shared.global [%0],[%1],16;" :: "r"(d), "l"(s));
}
#define CP_COMMIT asm volatile("cp.async.commit_group;")
#define CP_WAIT0  asm volatile("cp.async.wait_group 0;")

__device__ __forceinline__ float leaky(float v) { return v >= 0.f ? v : 0.01f * v; }
__device__ __forceinline__ float relu(float v)  { return v > 0.f ? v : 0.f; }
__device__ __forceinline__ uint32_t h2u(__half2 h) { return *(uint32_t*)&h; }

// stage one k32 chunk of a [K][N] fp16 weight matrix (256 threads)
template<int N, int WSN>
__device__ __forceinline__ void stageW(const __half* gw, int chunk, uint32_t dst, int tid) {
    const int ROWU = N / 8;
    const int TOT = 32 * ROWU;
    for (int u = tid; u < TOT; u += 256) {
        int r = u / ROWU, s = u - r * ROWU;
        cpa16(dst + (r * WSN + s * 8) * 2, gw + (size_t)(chunk * 32 + r) * N + s * 8);
    }
}

// 1-term fp16 GEMM, double-buffered. Caller must have staged+committed chunk 0 into buf 0.
template<int CH, int NFRG, int N, int WSN, int PL>
__device__ __forceinline__ void run_gemm(uint32_t aBase, uint32_t wst, const __half* gW,
                                         float (&acc)[2][NFRG * 2][4],
                                         int wm, int wn, int lane, int tid) {
    const uint32_t aoff = (uint32_t)(((wm * 32 + (lane & 15)) * AP + (lane >> 4) * 8) * 2);
    const int bg = lane >> 3, bi = lane & 7;
    const uint32_t boff = (uint32_t)((((bg & 1) * 8 + bi) * WSN + (bg >> 1) * 8) * 2);
    #pragma unroll 1
    for (int c = 0; c < CH; c++) {
        CP_WAIT0;
        __syncthreads();               // chunk c visible; buffer (c+1)&1 free
        if (c + 1 < CH) {
            stageW<N, WSN>(gW, c + 1, wst + ((c + 1) & 1) * PL, tid);
            CP_COMMIT;
        }
        const uint32_t wb = wst + (c & 1) * PL;
        #pragma unroll
        for (int ks = 0; ks < 2; ks++) {
            uint32_t ab = aBase + aoff + (uint32_t)(c * 2 + ks) * 32;
            uint32_t a0[4], a1[4];
            ldmA(ab, a0);
            ldmA(ab + 16 * AP * 2, a1);
            const uint32_t kb = wb + boff + (uint32_t)ks * 16 * WSN * 2;
            #pragma unroll
            for (int ng = 0; ng < NFRG; ng++) {
                uint32_t nb2 = (uint32_t)(((wn * NFRG + ng) * 16) * 2);
                uint32_t bh[4];
                ldmBT(kb + nb2, bh);
                mma(acc[0][ng * 2 + 0], a0, bh[0], bh[1]);
                mma(acc[0][ng * 2 + 1], a0, bh[2], bh[3]);
                mma(acc[1][ng * 2 + 0], a1, bh[0], bh[1]);
                mma(acc[1][ng * 2 + 1], a1, bh[2], bh[3]);
            }
        }
        __syncthreads();               // release read buffer
    }
}

// ---------------- prep: repack weights to fp16 [k][o] ----------------
__global__ void prep_kernel(const float* __restrict__ w1, const float* __restrict__ w2,
                            const float* __restrict__ w3, const float* __restrict__ w4) {
    int idx = blockIdx.x * blockDim.x + threadIdx.x;
    int stride = gridDim.x * blockDim.x;
    // layer 1 combined K=288: k<256 NDI weight (i=k>>4,j=k&15); 256..271: -wr[i]; 272..287: +wc[j]
    for (int t = idx; t < 288 * 256; t += stride) {
        int k = t >> 8, o = t & 255;
        float v;
        if (k < 256) {
            int i = k >> 4, j = k & 15;
            v = w1[o * 512 + i * 32 + j * 2 + 1];
        } else if (k < 272) {
            int i = k - 256; float s = 0.f;
            #pragma unroll
            for (int j = 0; j < 16; j++) s += w1[o * 512 + i * 32 + j * 2];
            v = -s;
        } else {
            int j = k - 272; float s = 0.f;
            #pragma unroll
            for (int i = 0; i < 16; i++) s += w1[o * 512 + i * 32 + j * 2];
            v = s;
        }
        g_W1[t] = __float2half_rn(v);
    }
    for (int t = idx; t < 256 * 128; t += stride) {
        int k = t >> 7, o = t & 127;
        g_W2[t] = __float2half_rn(w2[o * 256 + k]);
    }
    for (int t = idx; t < 128 * 64; t += stride) {
        int k = t >> 6, o = t & 63;
        g_W3[t] = __float2half_rn(w3[o * 128 + k]);
    }
    for (int t = idx; t < 256; t += stride) g_w4t[t] = w4[(t & 3) * 64 + (t >> 2)];
}

// ---------------- zero accumulators (graph-replay safe) ----------------
__global__ void zero_kernel() {
    int i = blockIdx.x * blockDim.x + threadIdx.x;
    if (i < NB * 132) g_acc[i] = 0.f;
}

// ---------------- main fused kernel: one CTA per (batch, 64-pos tile), 2 CTA/SM ----------------
__global__ __launch_bounds__(256, 2) void mlp_kernel(const float* __restrict__ x,
                                                     const float* __restrict__ b1,
                                                     const float* __restrict__ b2,
                                                     const float* __restrict__ b3,
                                                     const float* __restrict__ b4) {
    extern __shared__ char smem[];
    float* s_xp = (float*)smem;              // 320 floats; reused as s_e later
    float* s_e  = (float*)smem;              // 256 floats (exp weights), after xp is dead
    float* s_w4 = (float*)(smem + W4_OFF);   // 256 floats w4t
    __half* s_A = (__half*)(smem + A_OFF);
    float* s_h3 = (float*)(smem + W_OFF);    // staging area reuse after L3 GEMM: [64][68]
    float* s_part = (float*)(smem + W_OFF + 20480);  // 256 floats partial sums
    const uint32_t sb = cvta_s(smem);
    const uint32_t aBase = sb + A_OFF, wst = sb + W_OFF;

    const int b = blockIdx.x, pos0 = blockIdx.y * 64, tid = threadIdx.x;
    const int lane = tid & 31, ww = tid >> 5;
    const int wm = ww >> 2, wn = ww & 3;     // 2 m-warps x 4 n-warps
    const int r0 = lane >> 2, c0 = (lane & 3) * 2;
    // stmatrix per-lane base: rows wm*32 + (lane&15), col offset (lane>>4)*8
    const uint32_t stBase = aBase + (uint32_t)(((wm * 32 + (lane & 15)) * AP + (lane >> 4) * 8) * 2);

    // stage L1 chunk0 early
    stageW<256, WS1>(g_W1, 0, wst, tid); CP_COMMIT;

    // padded input row + w4 table
    for (int i = tid; i < 320; i += 256) {
        float v = 0.f;
        if (i >= 2 && i < 302) v = x[b * NFX + i - 2];
        s_xp[i] = v;
    }
    s_w4[tid] = g_w4t[tid];
    __syncthreads();

    // ---- build A (fp16) [64 x 288]: 4 threads per row, 72 contiguous k each ----
    {
        const int m = tid >> 2, k0 = (tid & 3) * 72;
        const int p = pos0 + m, h = p / 19, w = p - h * 19;
        const bool pv = (p < NP);
        __half* dst = s_A + m * AP;
        #pragma unroll 4
        for (int kk = 0; kk < 72; kk++) {
            int k = k0 + kk;
            float val = 0.f;
            if (pv) {
                if (k < 256) {
                    int i = k >> 4, j = k & 15;
                    float u = s_xp[i * 19 + h], v = s_xp[j * 19 + w];
                    val = __fdividef(v - u, u + v + EPS);
                } else if (k < 272) {
                    val = s_xp[(k - 256) * 19 + h];
                } else {
                    val = s_xp[(k - 272) * 19 + w];
                }
            }
            dst[k] = __float2half_rn(val);
        }
    }
    // (run_gemm's first internal __syncthreads orders A writes before ldmatrix)

    // ================= layer 1: K=288 -> 256 =================
    {
        float acc[2][8][4] = {};
        run_gemm<9, 4, 256, WS1, PL1>(aBase, wst, g_W1, acc, wm, wn, lane, tid);
        stageW<128, WS2>(g_W2, 0, wst, tid); CP_COMMIT;  // pre-stage L2
        // epilogue via stmatrix: one 16x16 tile per (mf, ng)
        #pragma unroll
        for (int mf = 0; mf < 2; mf++) {
            #pragma unroll
            for (int ng = 0; ng < 4; ng++) {
                int colb = (wn * 4 + ng) * 16;
                const float* a0 = acc[mf][ng * 2 + 0];
                const float* a1 = acc[mf][ng * 2 + 1];
                float e0b0 = __ldg(b1 + colb + c0),     e0b1 = __ldg(b1 + colb + c0 + 1);
                float e1b0 = __ldg(b1 + colb + 8 + c0), e1b1 = __ldg(b1 + colb + 8 + c0 + 1);
                uint32_t r0v = h2u(__floats2half2_rn(leaky(a0[0] + e0b0), leaky(a0[1] + e0b1)));
                uint32_t r1v = h2u(__floats2half2_rn(leaky(a0[2] + e0b0), leaky(a0[3] + e0b1)));
                uint32_t r2v = h2u(__floats2half2_rn(leaky(a1[0] + e1b0), leaky(a1[1] + e1b1)));
                uint32_t r3v = h2u(__floats2half2_rn(leaky(a1[2] + e1b0), leaky(a1[3] + e1b1)));
                stmA(stBase + (uint32_t)((mf * 16 * AP + colb) * 2), r0v, r1v, r2v, r3v);
            }
        }
    }
    __syncthreads();

    // ================= layer 2: K=256 -> 128 =================
    {
        float acc[2][4][4] = {};
        run_gemm<8, 2, 128, WS2, PL2>(aBase, wst, g_W2, acc, wm, wn, lane, tid);
        stageW<64, WS3>(g_W3, 0, wst, tid); CP_COMMIT;   // pre-stage L3
        #pragma unroll
        for (int mf = 0; mf < 2; mf++) {
            #pragma unroll
            for (int ng = 0; ng < 2; ng++) {
                int colb = (wn * 2 + ng) * 16;
                const float* a0 = acc[mf][ng * 2 + 0];
                const float* a1 = acc[mf][ng * 2 + 1];
                float e0b0 = __ldg(b2 + colb + c0),     e0b1 = __ldg(b2 + colb + c0 + 1);
                float e1b0 = __ldg(b2 + colb + 8 + c0), e1b1 = __ldg(b2 + colb + 8 + c0 + 1);
                uint32_t r0v = h2u(__floats2half2_rn(leaky(a0[0] + e0b0), leaky(a0[1] + e0b1)));
                uint32_t r1v = h2u(__floats2half2_rn(leaky(a0[2] + e0b0), leaky(a0[3] + e0b1)));
                uint32_t r2v = h2u(__floats2half2_rn(leaky(a1[0] + e1b0), leaky(a1[1] + e1b1)));
                uint32_t r3v = h2u(__floats2half2_rn(leaky(a1[2] + e1b0), leaky(a1[3] + e1b1)));
                stmA(stBase + (uint32_t)((mf * 16 * AP + colb) * 2), r0v, r1v, r2v, r3v);
            }
        }
    }
    __syncthreads();

    // ================= layer 3: K=128 -> 64 =================
    {
        float acc[2][2][4] = {};
        run_gemm<4, 1, 64, WS3, PL3>(aBase, wst, g_W3, acc, wm, wn, lane, tid);
        #pragma unroll
        for (int mf = 0; mf < 2; mf++) {
            int rb = wm * 32 + mf * 16 + r0;
            #pragma unroll
            for (int e = 0; e < 2; e++) {
                int col = wn * 16 + e * 8 + c0;
                const float* a = acc[mf][e];
                float bb0 = __ldg(b3 + col), bb1 = __ldg(b3 + col + 1);
                *(float2*)(s_h3 + rb * 68 + col) = make_float2(relu(a[0] + bb0), relu(a[1] + bb1));
                *(float2*)(s_h3 + (rb + 8) * 68 + col) = make_float2(relu(a[2] + bb0), relu(a[3] + bb1));
            }
        }
    }
    __syncthreads();

    // ================= layer 4: logits -> unnormalized exp weights =================
    {
        int m = tid >> 2, oh = tid & 3;      // 256 threads cover 64 rows x 4 heads
        float acc = __ldg(b4 + oh);
        const float* h3 = s_h3 + m * 68;
        #pragma unroll 16
        for (int c = 0; c < 64; c++) acc += h3[c] * s_w4[c * 4 + oh];
        float ev = __expf(relu(acc));
        if (pos0 + m >= NP) ev = 0.f;        // padding rows contribute nothing
        s_e[m * 4 + oh] = ev;
    }
    __syncthreads();

    // ================= fused softmax partials: num[c], den[head] =================
    {
        int c = tid & 127, half = tid >> 7;  // 2 m-halves per channel
        int head = c >> 5;
        float sum = 0.f;
        #pragma unroll 8
        for (int m = half * 32; m < half * 32 + 32; m++)
            sum += s_e[m * 4 + head] * __half2float(s_A[m * AP + c]);
        s_part[half * 128 + c] = sum;
    }
    __syncthreads();
    if (tid < 128) atomicAdd(&g_acc[b * 132 + tid], s_part[tid] + s_part[128 + tid]);
    if (tid < 4) {
        float d = 0.f;
        #pragma unroll 16
        for (int m = 0; m < 64; m++) d += s_e[m * 4 + tid];
        atomicAdd(&g_acc[b * 132 + 128 + tid], d);
    }
}

// ---------------- final divide ----------------
__global__ __launch_bounds__(128) void final_kernel(float* __restrict__ out) {
    int b = blockIdx.x, c = threadIdx.x;
    out[b * 128 + c] = g_acc[b * 132 + c] / g_acc[b * 132 + 128 + (c >> 5)];
}

// ---------------- launch ----------------
extern "C" void kernel_launch(void* const* d_in, const int* in_sizes, int n_in,
                              void* d_out, int out_size) {
    const float* x  = (const float*)d_in[0];
    const float* w1 = (const float*)d_in[1];
    const float* b1 = (const float*)d_in[2];
    const float* w2 = (const float*)d_in[3];
    const float* b2 = (const float*)d_in[4];
    const float* w3 = (const float*)d_in[5];
    const float* b3 = (const float*)d_in[6];
    const float* w4 = (const float*)d_in[7];
    const float* b4 = (const float*)d_in[8];
    float* out = (float*)d_out;

    cudaFuncSetAttribute(mlp_kernel, cudaFuncAttributeMaxDynamicSharedMemorySize, SMEM_TOTAL);

    prep_kernel<<<512, 256>>>(w1, w2, w3, w4);
    zero_kernel<<<(NB * 132 + 255) / 256, 256>>>();
    mlp_kernel<<<dim3(NB, 6), 256, SMEM_TOTAL>>>(x, b1, b2, b3, b4);
    final_kernel<<<NB, 128>>>(out);
}